// round 1
// baseline (speedup 1.0000x reference)
#include <cuda_runtime.h>
#include <cstdint>

#define NN 100000

// ---------------- static scratch (no allocs allowed) ----------------
__device__ float d_bufA[NN * 64];    // y1 / y3 (aggregated 64-dim)
__device__ float d_bufB[NN * 128];   // g1 / m1 (post W1+relu)
__device__ float d_bufC[NN * 64];    // h2 / h4 (post W2, pre-agg)
__device__ float d_bufD[NN * 64];    // g2
__device__ int   d_degb[NN];
__device__ int   d_degm[NN];
__device__ float d_dinvb[NN];
__device__ float d_dinvm[NN];
__device__ int   d_is64;

// ---------------- index dtype detection (int64 vs int32) ----------------
// If edges are int64 (little-endian), every high 32-bit word is 0 (values < 1e5).
// If int32, the "high words" are random values in [0,1e5): P(64 all zero) ~ 0.
__global__ void detect_kernel(const void* __restrict__ ei) {
    const int* w = (const int*)ei;
    int ok = 1;
    for (int i = 0; i < 64; i++)
        if (w[2 * i + 1] != 0) ok = 0;
    d_is64 = ok;
}

__device__ __forceinline__ int load_dst(const void* ei, long i, long nE) {
    if (d_is64) return (int)((const long long*)ei)[nE + i];
    return ((const int*)ei)[nE + i];
}
__device__ __forceinline__ int2 load_edge(const void* ei, long e, long nE) {
    if (d_is64) {
        const long long* p = (const long long*)ei;
        return make_int2((int)p[e], (int)p[nE + e]);
    }
    const int* p = (const int*)ei;
    return make_int2(p[e], p[nE + e]);
}

// ---------------- degree / dinv ----------------
__global__ void setone_kernel(int* __restrict__ deg, int n) {
    int i = blockIdx.x * blockDim.x + threadIdx.x;
    if (i < n) deg[i] = 1;  // self loop
}
__global__ void count_deg_kernel(const void* __restrict__ ei, long nE, int* __restrict__ deg) {
    long i = blockIdx.x * (long)blockDim.x + threadIdx.x;
    if (i >= nE) return;
    atomicAdd(&deg[load_dst(ei, i, nE)], 1);
}
__global__ void dinv_kernel(const int* __restrict__ deg, float* __restrict__ dinv, int n) {
    int i = blockIdx.x * blockDim.x + threadIdx.x;
    if (i < n) dinv[i] = rsqrtf((float)deg[i]);
}

// ---------------- self-loop init: out[i] = h[i]/deg[i] (+ bias) ----------------
template <bool BIAS>
__global__ void init_self_kernel(const float* __restrict__ h, float* __restrict__ out,
                                 const int* __restrict__ deg, const float* __restrict__ bias,
                                 int n) {
    long idx = blockIdx.x * (long)blockDim.x + threadIdx.x;
    if (idx >= (long)n * 16) return;
    int row = (int)(idx >> 4);
    int c = (int)(idx & 15) * 4;
    float s = 1.0f / (float)deg[row];
    float4 v = *(const float4*)(h + (long)row * 64 + c);
    float4 o;
    o.x = v.x * s; o.y = v.y * s; o.z = v.z * s; o.w = v.w * s;
    if (BIAS) {
        o.x += bias[c + 0]; o.y += bias[c + 1];
        o.z += bias[c + 2]; o.w += bias[c + 3];
    }
    *(float4*)(out + (long)row * 64 + c) = o;
}

// ---------------- edge aggregation (64-dim): out[dst] += h[src]*dinv[s]*dinv[d] ----------------
// 16 threads per edge, float4 per thread, vector reduction to L2 (sm_90+ red.v4.f32).
__global__ void agg_kernel(const float* __restrict__ h, float* __restrict__ out,
                           const void* __restrict__ ei, long nE,
                           const float* __restrict__ dinv) {
    long gid = blockIdx.x * (long)blockDim.x + threadIdx.x;
    long e = gid >> 4;
    if (e >= nE) return;
    int c = (int)(gid & 15) * 4;
    int2 sd = load_edge(ei, e, nE);
    float nrm = dinv[sd.x] * dinv[sd.y];
    float4 v = *(const float4*)(h + (long)sd.x * 64 + c);
    float* dp = out + (long)sd.y * 64 + c;
    asm volatile("red.global.add.v4.f32 [%0], {%1,%2,%3,%4};"
                 :: "l"(dp), "f"(v.x * nrm), "f"(v.y * nrm), "f"(v.z * nrm), "f"(v.w * nrm)
                 : "memory");
}

// ---------------- SGEMM: C[N,FOUT] = A[N,FIN] @ W[FIN,FOUT] (+bias, relu) ----------------
// Block: 256 threads handle 64 rows; W + A tile in dynamic smem; 4 x NR register tile.
template <int FIN, int FOUT, bool BR>
__launch_bounds__(256) __global__
void gemm_kernel(const float* __restrict__ A, const float* __restrict__ W,
                 const float* __restrict__ bias, float* __restrict__ C, int N) {
    constexpr int NR = FOUT / 16;   // 8 (FOUT=128) or 4 (FOUT=64)
    constexpr int AST = FIN + 4;    // padded smem stride
    extern __shared__ float sm[];
    float* As = sm;                 // 64*AST
    float* Ws = sm + 64 * AST;      // FIN*FOUT

    const int t = threadIdx.x;
    const int row0 = blockIdx.x * 64;

    for (int i = t * 4; i < FIN * FOUT; i += 256 * 4)
        *(float4*)(Ws + i) = *(const float4*)(W + i);

    constexpr int AVEC = 64 * FIN / 4;
    for (int i = t; i < AVEC; i += 256) {
        int r = i / (FIN / 4), k4 = (i % (FIN / 4)) * 4;
        float4 v = make_float4(0.f, 0.f, 0.f, 0.f);
        if (row0 + r < N) v = *(const float4*)(A + (long)(row0 + r) * FIN + k4);
        *(float4*)(As + r * AST + k4) = v;
    }
    __syncthreads();

    const int rg = t >> 4, cg = t & 15;
    float acc[4][NR];
    #pragma unroll
    for (int i = 0; i < 4; i++)
        #pragma unroll
        for (int j = 0; j < NR; j++) acc[i][j] = 0.f;

    const float* a0p = As + (rg * 4 + 0) * AST;
    const float* a1p = As + (rg * 4 + 1) * AST;
    const float* a2p = As + (rg * 4 + 2) * AST;
    const float* a3p = As + (rg * 4 + 3) * AST;
    const float* wp = Ws + cg * NR;

    #pragma unroll 8
    for (int k = 0; k < FIN; k++) {
        float a0 = a0p[k], a1 = a1p[k], a2 = a2p[k], a3 = a3p[k];
        float w[NR];
        #pragma unroll
        for (int j = 0; j < NR; j += 4)
            *(float4*)(w + j) = *(const float4*)(wp + k * FOUT + j);
        #pragma unroll
        for (int j = 0; j < NR; j++) {
            acc[0][j] += a0 * w[j];
            acc[1][j] += a1 * w[j];
            acc[2][j] += a2 * w[j];
            acc[3][j] += a3 * w[j];
        }
    }

    float bb[NR];
    if (BR) {
        #pragma unroll
        for (int j = 0; j < NR; j++) bb[j] = bias[cg * NR + j];
    }
    #pragma unroll
    for (int i = 0; i < 4; i++) {
        int r = row0 + rg * 4 + i;
        if (r < N) {
            #pragma unroll
            for (int j = 0; j < NR; j += 4) {
                float4 o;
                o.x = acc[i][j + 0]; o.y = acc[i][j + 1];
                o.z = acc[i][j + 2]; o.w = acc[i][j + 3];
                if (BR) {
                    o.x = fmaxf(o.x + bb[j + 0], 0.f);
                    o.y = fmaxf(o.y + bb[j + 1], 0.f);
                    o.z = fmaxf(o.z + bb[j + 2], 0.f);
                    o.w = fmaxf(o.w + bb[j + 3], 0.f);
                }
                *(float4*)(C + (long)r * FOUT + cg * NR + j) = o;
            }
        }
    }
}

// ---------------- log_softmax over 64 cols, in-place, one warp per row ----------------
__global__ void logsoftmax_kernel(float* __restrict__ io, int n) {
    int row = blockIdx.x * (blockDim.x / 32) + (threadIdx.x >> 5);
    if (row >= n) return;
    int lane = threadIdx.x & 31;
    float* p = io + (long)row * 64;
    float v0 = p[lane], v1 = p[lane + 32];
    float m = fmaxf(v0, v1);
    #pragma unroll
    for (int off = 16; off > 0; off >>= 1)
        m = fmaxf(m, __shfl_xor_sync(0xFFFFFFFFu, m, off));
    float s = __expf(v0 - m) + __expf(v1 - m);
    #pragma unroll
    for (int off = 16; off > 0; off >>= 1)
        s += __shfl_xor_sync(0xFFFFFFFFu, s, off);
    float l = m + __logf(s);
    p[lane] = v0 - l;
    p[lane + 32] = v1 - l;
}

// ---------------- launch ----------------
static inline long cdiv(long a, long b) { return (a + b - 1) / b; }

extern "C" void kernel_launch(void* const* d_in, const int* in_sizes, int n_in,
                              void* d_out, int out_size) {
    const float* x = (const float*)d_in[0];
    const void* ei = d_in[1];
    const void* mei = d_in[2];
    const float* W1 = (const float*)d_in[3];
    const float* b1 = (const float*)d_in[4];
    const float* W2 = (const float*)d_in[5];
    const float* b2 = (const float*)d_in[6];
    const long nE = in_sizes[1] / 2;
    const long nM = in_sizes[2] / 2;
    const int n = in_sizes[0] / 64;
    float* out = (float*)d_out;

    float *bufA, *bufB, *bufC, *bufD, *dinvb, *dinvm;
    int *degb, *degm;
    cudaGetSymbolAddress((void**)&bufA, d_bufA);
    cudaGetSymbolAddress((void**)&bufB, d_bufB);
    cudaGetSymbolAddress((void**)&bufC, d_bufC);
    cudaGetSymbolAddress((void**)&bufD, d_bufD);
    cudaGetSymbolAddress((void**)&degb, d_degb);
    cudaGetSymbolAddress((void**)&degm, d_degm);
    cudaGetSymbolAddress((void**)&dinvb, d_dinvb);
    cudaGetSymbolAddress((void**)&dinvm, d_dinvm);

    const int SM1 = (64 * (64 + 4) + 64 * 128) * 4;    // gemm<64,128>
    const int SM2 = (64 * (128 + 4) + 128 * 64) * 4;   // gemm<128,64>
    cudaFuncSetAttribute(gemm_kernel<64, 128, true>,
                         cudaFuncAttributeMaxDynamicSharedMemorySize, SM1);
    cudaFuncSetAttribute(gemm_kernel<128, 64, false>,
                         cudaFuncAttributeMaxDynamicSharedMemorySize, SM2);

    detect_kernel<<<1, 1>>>(ei);

    // degrees + dinv for both graphs
    setone_kernel<<<cdiv(n, 256), 256>>>(degb, n);
    setone_kernel<<<cdiv(n, 256), 256>>>(degm, n);
    count_deg_kernel<<<cdiv(nE, 256), 256>>>(ei, nE, degb);
    count_deg_kernel<<<cdiv(nM, 256), 256>>>(mei, nM, degm);
    dinv_kernel<<<cdiv(n, 256), 256>>>(degb, dinvb, n);
    dinv_kernel<<<cdiv(n, 256), 256>>>(degm, dinvm, n);

    const long initB = cdiv((long)n * 16, 256);
    const long gemB = cdiv(n, 64);

    // conv1: y1 = A_hat x  (aggregate in 64-dim, then GEMM)  g1 = relu(y1 W1 + b1)
    init_self_kernel<false><<<initB, 256>>>(x, bufA, degb, nullptr, n);
    agg_kernel<<<cdiv(nE * 16, 256), 256>>>(x, bufA, ei, nE, dinvb);
    gemm_kernel<64, 128, true><<<gemB, 256, SM1>>>(bufA, W1, b1, bufB, n);

    // conv2: h2 = g1 W2 ; g2 = A_hat h2 + b2  (GEMM first: output is 64-dim)
    gemm_kernel<128, 64, false><<<gemB, 256, SM2>>>(bufB, W2, nullptr, bufC, n);
    init_self_kernel<true><<<initB, 256>>>(bufC, bufD, degb, b2, n);
    agg_kernel<<<cdiv(nE * 16, 256), 256>>>(bufC, bufD, ei, nE, dinvb);

    // conv3 (meta): y3 = A_hat_m g2 ; m1 = relu(y3 W1 + b1)
    init_self_kernel<false><<<initB, 256>>>(bufD, bufA, degm, nullptr, n);
    agg_kernel<<<cdiv(nM * 16, 256), 256>>>(bufD, bufA, mei, nM, dinvm);
    gemm_kernel<64, 128, true><<<gemB, 256, SM1>>>(bufA, W1, b1, bufB, n);

    // conv4 (meta): h4 = m1 W2 ; m2 = A_hat_m h4 + b2  (directly into d_out)
    gemm_kernel<128, 64, false><<<gemB, 256, SM2>>>(bufB, W2, nullptr, bufC, n);
    init_self_kernel<true><<<initB, 256>>>(bufC, out, degm, b2, n);
    agg_kernel<<<cdiv(nM * 16, 256), 256>>>(bufC, out, mei, nM, dinvm);

    // final log_softmax, in place on d_out
    logsoftmax_kernel<<<cdiv(n, 8), 256>>>(out, n);
}

// round 3
// speedup vs baseline: 1.3237x; 1.3237x over previous
#include <cuda_runtime.h>
#include <cstdint>

#define NN 100000

// ---------------- static scratch (no allocs allowed) ----------------
__device__ float d_bufA[NN * 64];    // aggregated 64-dim
__device__ float d_bufB[NN * 128];   // post W1+relu
__device__ float d_bufC[NN * 64];    // post W2, pre-agg
__device__ float d_bufD[NN * 64];    // g2
__device__ int   d_degb[NN];
__device__ int   d_degm[NN];
__device__ float d_dinvb[NN];
__device__ float d_dinvm[NN];
__device__ int   d_is64;

// ---------------- index dtype detection (int64 vs int32) ----------------
__global__ void detect_kernel(const void* __restrict__ ei) {
    const int* w = (const int*)ei;
    int ok = 1;
    for (int i = 0; i < 64; i++)
        if (w[2 * i + 1] != 0) ok = 0;
    d_is64 = ok;
}

__device__ __forceinline__ int load_dst(const void* ei, long i, long nE) {
    if (d_is64) return (int)((const long long*)ei)[nE + i];
    return ((const int*)ei)[nE + i];
}
__device__ __forceinline__ int2 load_edge(const void* ei, long e, long nE) {
    if (d_is64) {
        const long long* p = (const long long*)ei;
        return make_int2((int)p[e], (int)p[nE + e]);
    }
    const int* p = (const int*)ei;
    return make_int2(p[e], p[nE + e]);
}

// ---------------- degree / dinv ----------------
__global__ void setone_kernel(int* __restrict__ deg, int n) {
    int i = blockIdx.x * blockDim.x + threadIdx.x;
    if (i < n) deg[i] = 1;
}
__global__ void count_deg_kernel(const void* __restrict__ ei, long nE, int* __restrict__ deg) {
    long i = blockIdx.x * (long)blockDim.x + threadIdx.x;
    if (i >= nE) return;
    atomicAdd(&deg[load_dst(ei, i, nE)], 1);
}
__global__ void dinv_kernel(const int* __restrict__ deg, float* __restrict__ dinv, int n) {
    int i = blockIdx.x * blockDim.x + threadIdx.x;
    if (i < n) dinv[i] = rsqrtf((float)deg[i]);
}

// ---------------- self-loop init: out[i] = h[i]/deg[i] (+ bias) ----------------
template <bool BIAS>
__global__ void init_self_kernel(const float* __restrict__ h, float* __restrict__ out,
                                 const int* __restrict__ deg, const float* __restrict__ bias,
                                 int n) {
    long idx = blockIdx.x * (long)blockDim.x + threadIdx.x;
    if (idx >= (long)n * 16) return;
    int row = (int)(idx >> 4);
    int c = (int)(idx & 15) * 4;
    float s = 1.0f / (float)deg[row];
    float4 v = *(const float4*)(h + (long)row * 64 + c);
    float4 o;
    o.x = v.x * s; o.y = v.y * s; o.z = v.z * s; o.w = v.w * s;
    if (BIAS) {
        o.x += bias[c + 0]; o.y += bias[c + 1];
        o.z += bias[c + 2]; o.w += bias[c + 3];
    }
    *(float4*)(out + (long)row * 64 + c) = o;
}

// ---------------- edge aggregation (64-dim) ----------------
__global__ void agg_kernel(const float* __restrict__ h, float* __restrict__ out,
                           const void* __restrict__ ei, long nE,
                           const float* __restrict__ dinv) {
    long gid = blockIdx.x * (long)blockDim.x + threadIdx.x;
    long e = gid >> 4;
    if (e >= nE) return;
    int c = (int)(gid & 15) * 4;
    int2 sd = load_edge(ei, e, nE);
    float nrm = dinv[sd.x] * dinv[sd.y];
    float4 v = *(const float4*)(h + (long)sd.x * 64 + c);
    float* dp = out + (long)sd.y * 64 + c;
    asm volatile("red.global.add.v4.f32 [%0], {%1,%2,%3,%4};"
                 :: "l"(dp), "f"(v.x * nrm), "f"(v.y * nrm), "f"(v.z * nrm), "f"(v.w * nrm)
                 : "memory");
}

// ---------------- tf32 tensor-core GEMM ----------------
// C[N,FOUT] = A[N,FIN] @ W[FIN,FOUT] (+bias,relu). M_TILE=128, 256 thr.
// Warps: 4 (M) x 2 (N); warp tile m32 x (FOUT/2).
// Smem holds fragment-permuted tf32 A and B so the inner loop is pure
// LDS.128/LDS.64 + mma.sync.m16n8k8.

__device__ __forceinline__ uint32_t f2tf32(float v) {
    uint32_t o;
    asm("cvt.rna.tf32.f32 %0, %1;" : "=r"(o) : "f"(v));
    return o;
}

__device__ __forceinline__ void mma_tf32(float* d, const uint32_t* a, const uint32_t* b) {
    asm volatile(
        "mma.sync.aligned.m16n8k8.row.col.f32.tf32.tf32.f32 "
        "{%0,%1,%2,%3},{%4,%5,%6,%7},{%8,%9},{%0,%1,%2,%3};"
        : "+f"(d[0]), "+f"(d[1]), "+f"(d[2]), "+f"(d[3])
        : "r"(a[0]), "r"(a[1]), "r"(a[2]), "r"(a[3]), "r"(b[0]), "r"(b[1]));
}

template <int FIN, int FOUT, bool BR>
__launch_bounds__(256) __global__
void mma_gemm_kernel(const float* __restrict__ A, const float* __restrict__ W,
                     const float* __restrict__ bias, float* __restrict__ C, int N) {
    constexpr int KS = FIN / 8;     // k-steps
    constexpr int NC = FOUT / 8;    // total n-chunks
    constexpr int NCW = NC / 2;     // n-chunks per warp
    extern __shared__ float sm[];
    float* As = sm;                       // 8 mfrags * KS * 32 * 4
    float* Bs = sm + 8 * KS * 128;        // KS * NC * 32 * 2

    const int t = threadIdx.x;
    const int row0 = blockIdx.x * 128;

    // --- load A tile, fragment-permuted, tf32-rounded ---
    for (int idx = t; idx < 128 * FIN; idx += 256) {
        int row = idx / FIN, col = idx % FIN;
        float v = (row0 + row < N) ? A[(long)(row0 + row) * FIN + col] : 0.f;
        int mf = row >> 4, r0 = row & 15;
        int ks = col >> 3;
        int th = ((r0 & 7) << 2) | (col & 3);
        int slot = (r0 >> 3) | (((col & 7) >> 2) << 1);
        As[(((mf * KS + ks) * 32 + th) << 2) | slot] = __uint_as_float(f2tf32(v));
    }
    // --- load B (weights), fragment-permuted, tf32-rounded ---
    for (int idx = t; idx < FIN * FOUT; idx += 256) {
        int k = idx / FOUT, nn = idx % FOUT;
        float v = W[idx];
        int ks = k >> 3;
        int th = ((nn & 7) << 2) | (k & 3);
        int slot = (k & 7) >> 2;
        int nc = nn >> 3;
        Bs[(((ks * NC + nc) * 32 + th) << 1) | slot] = __uint_as_float(f2tf32(v));
    }
    __syncthreads();

    const int w = t >> 5, lane = t & 31;
    const int mw = w & 3, nw = w >> 2;

    float acc[2][NCW][4];
    #pragma unroll
    for (int i = 0; i < 2; i++)
        #pragma unroll
        for (int j = 0; j < NCW; j++)
            #pragma unroll
            for (int q = 0; q < 4; q++) acc[i][j][q] = 0.f;

    #pragma unroll
    for (int ks = 0; ks < KS; ks++) {
        uint32_t a0[4], a1[4];
        *(float4*)a0 = *(const float4*)(As + ((((2 * mw + 0) * KS + ks) * 32 + lane) << 2));
        *(float4*)a1 = *(const float4*)(As + ((((2 * mw + 1) * KS + ks) * 32 + lane) << 2));
        #pragma unroll
        for (int nc = 0; nc < NCW; nc++) {
            uint32_t b[2];
            *(float2*)b = *(const float2*)(Bs + (((ks * NC + nw * NCW + nc) * 32 + lane) << 1));
            mma_tf32(acc[0][nc], a0, b);
            mma_tf32(acc[1][nc], a1, b);
        }
    }

    // --- epilogue ---
    const int cbase = nw * (NCW * 8) + (lane & 3) * 2;
    #pragma unroll
    for (int mi = 0; mi < 2; mi++) {
        int rfrag = row0 + (2 * mw + mi) * 16 + (lane >> 2);
        #pragma unroll
        for (int nc = 0; nc < NCW; nc++) {
            int cc = cbase + nc * 8;
            float2 bb = make_float2(0.f, 0.f);
            if (BR) bb = *(const float2*)(bias + cc);
            float2 lo = make_float2(acc[mi][nc][0], acc[mi][nc][1]);
            float2 hi = make_float2(acc[mi][nc][2], acc[mi][nc][3]);
            if (BR) {
                lo.x = fmaxf(lo.x + bb.x, 0.f); lo.y = fmaxf(lo.y + bb.y, 0.f);
                hi.x = fmaxf(hi.x + bb.x, 0.f); hi.y = fmaxf(hi.y + bb.y, 0.f);
            }
            if (rfrag < N)     *(float2*)(C + (long)rfrag * FOUT + cc) = lo;
            if (rfrag + 8 < N) *(float2*)(C + (long)(rfrag + 8) * FOUT + cc) = hi;
        }
    }
}

// ---------------- log_softmax over 64 cols ----------------
__global__ void logsoftmax_kernel(float* __restrict__ io, int n) {
    int row = blockIdx.x * (blockDim.x / 32) + (threadIdx.x >> 5);
    if (row >= n) return;
    int lane = threadIdx.x & 31;
    float* p = io + (long)row * 64;
    float v0 = p[lane], v1 = p[lane + 32];
    float m = fmaxf(v0, v1);
    #pragma unroll
    for (int off = 16; off > 0; off >>= 1)
        m = fmaxf(m, __shfl_xor_sync(0xFFFFFFFFu, m, off));
    float s = __expf(v0 - m) + __expf(v1 - m);
    #pragma unroll
    for (int off = 16; off > 0; off >>= 1)
        s += __shfl_xor_sync(0xFFFFFFFFu, s, off);
    float l = m + __logf(s);
    p[lane] = v0 - l;
    p[lane + 32] = v1 - l;
}

// ---------------- launch ----------------
static inline long cdiv(long a, long b) { return (a + b - 1) / b; }

extern "C" void kernel_launch(void* const* d_in, const int* in_sizes, int n_in,
                              void* d_out, int out_size) {
    const float* x = (const float*)d_in[0];
    const void* ei = d_in[1];
    const void* mei = d_in[2];
    const float* W1 = (const float*)d_in[3];
    const float* b1 = (const float*)d_in[4];
    const float* W2 = (const float*)d_in[5];
    const float* b2 = (const float*)d_in[6];
    const long nE = in_sizes[1] / 2;
    const long nM = in_sizes[2] / 2;
    const int n = in_sizes[0] / 64;
    float* out = (float*)d_out;

    float *bufA, *bufB, *bufC, *bufD, *dinvb, *dinvm;
    int *degb, *degm;
    cudaGetSymbolAddress((void**)&bufA, d_bufA);
    cudaGetSymbolAddress((void**)&bufB, d_bufB);
    cudaGetSymbolAddress((void**)&bufC, d_bufC);
    cudaGetSymbolAddress((void**)&bufD, d_bufD);
    cudaGetSymbolAddress((void**)&degb, d_degb);
    cudaGetSymbolAddress((void**)&degm, d_degm);
    cudaGetSymbolAddress((void**)&dinvb, d_dinvb);
    cudaGetSymbolAddress((void**)&dinvm, d_dinvm);

    // smem: A_perm = 8*KS*128 floats, B_perm = KS*NC*64 floats
    const int SM1 = (8 * 8 * 128 + 8 * 16 * 64) * 4;     // 64 KB  (FIN=64 ,FOUT=128)
    const int SM2 = (8 * 16 * 128 + 16 * 8 * 64) * 4;    // 96 KB  (FIN=128,FOUT=64)
    cudaFuncSetAttribute(mma_gemm_kernel<64, 128, true>,
                         cudaFuncAttributeMaxDynamicSharedMemorySize, SM1);
    cudaFuncSetAttribute(mma_gemm_kernel<128, 64, false>,
                         cudaFuncAttributeMaxDynamicSharedMemorySize, SM2);

    const long initB = cdiv((long)n * 16, 256);
    const long gemB = cdiv(n, 128);

    // base-graph prep (ordered so the ncu capture slot lands on agg/gemm)
    detect_kernel<<<1, 1>>>(ei);
    setone_kernel<<<cdiv(n, 256), 256>>>(degb, n);
    count_deg_kernel<<<cdiv(nE, 256), 256>>>(ei, nE, degb);
    dinv_kernel<<<cdiv(n, 256), 256>>>(degb, dinvb, n);

    // conv1: y1 = A_hat x ; g1 = relu(y1 W1 + b1)
    init_self_kernel<false><<<initB, 256>>>(x, bufA, degb, nullptr, n);
    agg_kernel<<<cdiv(nE * 16, 256), 256>>>(x, bufA, ei, nE, dinvb);     // <- capture target
    mma_gemm_kernel<64, 128, true><<<gemB, 256, SM1>>>(bufA, W1, b1, bufB, n);

    // conv2: h2 = g1 W2 ; g2 = A_hat h2 + b2
    mma_gemm_kernel<128, 64, false><<<gemB, 256, SM2>>>(bufB, W2, nullptr, bufC, n);
    init_self_kernel<true><<<initB, 256>>>(bufC, bufD, degb, b2, n);
    agg_kernel<<<cdiv(nE * 16, 256), 256>>>(bufC, bufD, ei, nE, dinvb);

    // meta-graph prep
    setone_kernel<<<cdiv(n, 256), 256>>>(degm, n);
    count_deg_kernel<<<cdiv(nM, 256), 256>>>(mei, nM, degm);
    dinv_kernel<<<cdiv(n, 256), 256>>>(degm, dinvm, n);

    // conv3: y3 = A_hat_m g2 ; m1 = relu(y3 W1 + b1)
    init_self_kernel<false><<<initB, 256>>>(bufD, bufA, degm, nullptr, n);
    agg_kernel<<<cdiv(nM * 16, 256), 256>>>(bufD, bufA, mei, nM, dinvm);
    mma_gemm_kernel<64, 128, true><<<gemB, 256, SM1>>>(bufA, W1, b1, bufB, n);

    // conv4: h4 = m1 W2 ; m2 = A_hat_m h4 + b2 (into d_out)
    mma_gemm_kernel<128, 64, false><<<gemB, 256, SM2>>>(bufB, W2, nullptr, bufC, n);
    init_self_kernel<true><<<initB, 256>>>(bufC, out, degm, b2, n);
    agg_kernel<<<cdiv(nM * 16, 256), 256>>>(bufC, out, mei, nM, dinvm);

    logsoftmax_kernel<<<cdiv(n, 8), 256>>>(out, n);
}